// round 9
// baseline (speedup 1.0000x reference)
#include <cuda_runtime.h>
#include <cstdint>

// LCC over [B=2,1,192,192,192] fp32, fully fused z-sweep.
// Round-9: per-row neighbor sync, ping-pong mbarriers (2/row/family),
// FULL-WARP arrive+wait (count=32) -- every lane's own release covers its
// stores, every lane's own acquire covers its loads. Fixes round-8's
// lane0-only visibility bug. Compute identical to the passing round-6 kernel.

namespace {
constexpr int NV   = 192;
constexpr int NV2  = NV * NV;
constexpr long long NV3 = (long long)NV * NV2;
constexpr int BYT  = 12;            // warps per block, 1 row each
constexpr int COVY = 12;
constexpr int TOUTY = 8;
constexpr int TOUTX = 48;           // lanes cover 64 x (float2)
constexpr int ZCHUNKS = 8;
constexpr int ZC   = NV / ZCHUNKS;  // 24
constexpr float EPSV  = 1e-5f;
constexpr float INV27 = 1.0f / 27.0f;
constexpr unsigned FULL = 0xffffffffu;
}

__device__ __forceinline__ float2 a2(float2 a, float2 b) {
    float2 r;
    asm("{.reg .b64 ra,rb,rc;\n\t"
        "mov.b64 ra,{%2,%3};\n\t"
        "mov.b64 rb,{%4,%5};\n\t"
        "add.rn.f32x2 rc,ra,rb;\n\t"
        "mov.b64 {%0,%1},rc;}\n\t"
        : "=f"(r.x), "=f"(r.y)
        : "f"(a.x), "f"(a.y), "f"(b.x), "f"(b.y));
    return r;
}
__device__ __forceinline__ float2 m2(float2 a, float2 b) {
    float2 r;
    asm("{.reg .b64 ra,rb,rc;\n\t"
        "mov.b64 ra,{%2,%3};\n\t"
        "mov.b64 rb,{%4,%5};\n\t"
        "mul.rn.f32x2 rc,ra,rb;\n\t"
        "mov.b64 {%0,%1},rc;}\n\t"
        : "=f"(r.x), "=f"(r.y)
        : "f"(a.x), "f"(a.y), "f"(b.x), "f"(b.y));
    return r;
}
__device__ __forceinline__ float2 f2ma(float2 a, float2 b, float2 c) {
    float2 r;
    asm("{.reg .b64 ra,rb,rc,rd;\n\t"
        "mov.b64 ra,{%2,%3};\n\t"
        "mov.b64 rb,{%4,%5};\n\t"
        "mov.b64 rc,{%6,%7};\n\t"
        "fma.rn.f32x2 rd,ra,rb,rc;\n\t"
        "mov.b64 {%0,%1},rd;}\n\t"
        : "=f"(r.x), "=f"(r.y)
        : "f"(a.x), "f"(a.y), "f"(b.x), "f"(b.y), "f"(c.x), "f"(c.y));
    return r;
}

__device__ __forceinline__ uint32_t s2u(const void* p) {
    uint32_t a;
    asm("{ .reg .u64 t; cvta.to.shared.u64 t, %1; cvt.u32.u64 %0, t; }"
        : "=r"(a) : "l"(p));
    return a;
}
__device__ __forceinline__ void mb_init(uint32_t a, uint32_t c) {
    asm volatile("mbarrier.init.shared.b64 [%0], %1;" :: "r"(a), "r"(c) : "memory");
}
__device__ __forceinline__ void mb_arrive(uint32_t a) {
    asm volatile("mbarrier.arrive.release.cta.shared.b64 _, [%0];" :: "r"(a) : "memory");
}
__device__ __forceinline__ void mb_wait(uint32_t a, uint32_t parity) {
    uint32_t done;
    asm volatile(
        "{\n\t.reg .pred p;\n\t"
        "mbarrier.try_wait.parity.acquire.cta.shared::cta.b64 p, [%1], %2, 0x989680;\n\t"
        "selp.b32 %0, 1, 0, p;\n\t}"
        : "=r"(done) : "r"(a), "r"(parity) : "memory");
    while (!done) {
        asm volatile(
            "{\n\t.reg .pred p;\n\t"
            "mbarrier.try_wait.parity.acquire.cta.shared::cta.b64 p, [%1], %2, 0x989680;\n\t"
            "selp.b32 %0, 1, 0, p;\n\t}"
            : "=r"(done) : "r"(a), "r"(parity) : "memory");
    }
}

__global__ void zero_out_kernel(float* out, int n) {
    int i = blockIdx.x * blockDim.x + threadIdx.x;
    if (i < n) out[i] = 0.0f;
}

__global__ __launch_bounds__(32 * BYT, 2)
void lcc_kernel(const float* __restrict__ gF,
                const float* __restrict__ gM,
                float* __restrict__ out)
{
    __shared__ float2 sA [2][COVY][33];
    __shared__ float2 sB [2][COVY][33];
    __shared__ float2 sQ0[2][COVY][33];
    __shared__ float2 sQ1[2][COVY][33];
    __shared__ float2 sQ2[2][COVY][33];
    __shared__ unsigned long long mbS[2][COVY];   // ping-pong per row
    __shared__ unsigned long long mbQ[2][COVY];
    __shared__ float wsum[BYT];

    const int tx = threadIdx.x;
    const int ty = threadIdx.y;
    const int b  = blockIdx.z / ZCHUNKS;
    const int Z0 = (blockIdx.z % ZCHUNKS) * ZC;

    if (tx == 0 && ty == 0) {
        for (int r = 0; r < COVY; r++) {
            mb_init(s2u(&mbS[0][r]), 32);   // all 32 lanes arrive
            mb_init(s2u(&mbS[1][r]), 32);
            mb_init(s2u(&mbQ[0][r]), 32);
            mb_init(s2u(&mbQ[1][r]), 32);
        }
    }
    __syncthreads();

    const bool hasUp = (ty > 0);
    const bool hasDn = (ty < COVY - 1);
    const int tyu = hasUp ? ty - 1 : ty;
    const int tyd = hasDn ? ty + 1 : ty;

    const int x_nom0 = (int)blockIdx.x * TOUTX - 2 + 2 * tx;   // even
    const int xbase  = min(max(x_nom0, 0), NV - 2);
    const bool fixlo  = (x_nom0 < 0);
    const bool fixhi  = (x_nom0 > NV - 2);
    const bool fixXlo = (x_nom0 == 0);
    const bool fixXhi = (x_nom0 + 1 == NV - 1);

    const int y_nom = (int)blockIdx.y * TOUTY - 2 + ty;
    const bool fixYup = (y_nom == 0);
    const bool fixYdn = (y_nom == NV - 1);
    const int yoff = min(max(y_nom, 0), NV - 1) * NV + xbase;

    const float* F = gF + (long long)b * NV3;
    const float* M = gM + (long long)b * NV3;

    float2 rF[3], rM[3];
    float2 pA[3], pB[3], pC[3];
    float2 acc = make_float2(0.f, 0.f);
    unsigned sCnt = 0, qCnt = 0;   // phase counters (CTA-uniform progress)

    const float2 NEGI = make_float2(-INV27, -INV27);
    const float2 EPS2 = make_float2(EPSV, EPSV);

    const float mk = (tx >= 1 && tx <= 24 && ty >= 2 && ty < 2 + TOUTY) ? 1.0f : 0.0f;
    const float2 mask = make_float2(mk, mk);

    const int rup = ty ? ty - 1 : 0;
    const int rdn = (ty + 1 < COVY) ? ty + 1 : COVY - 1;

    auto loadp = [&](int z, int s) {
        z = min(max(z, 0), NV - 1);
        const float* fp = F + z * NV2;
        const float* mp = M + z * NV2;
        float2 vF = __ldg(reinterpret_cast<const float2*>(fp + yoff));
        float2 vM = __ldg(reinterpret_cast<const float2*>(mp + yoff));
        rF[s].x = fixhi ? vF.y : vF.x;  rF[s].y = fixlo ? vF.x : vF.y;
        rM[s].x = fixhi ? vM.y : vM.x;  rM[s].y = fixlo ? vM.x : vM.y;
    };

    // phase n of family X: ALL lanes arrive own mbX[n&1][ty]; ALL lanes wait
    // neighbors' mbX[n&1][ty +/- 1] with parity (n>>1)&1.
    auto exchS = [&](unsigned n) {
        const int bi = n & 1;
        const uint32_t pp = (n >> 1) & 1;
        mb_arrive(s2u(&mbS[bi][ty]));
        if (hasUp) mb_wait(s2u(&mbS[bi][tyu]), pp);
        if (hasDn) mb_wait(s2u(&mbS[bi][tyd]), pp);
        __syncwarp();
    };
    auto exchQ = [&](unsigned n) {
        const int bi = n & 1;
        const uint32_t pp = (n >> 1) & 1;
        mb_arrive(s2u(&mbQ[bi][ty]));
        if (hasUp) mb_wait(s2u(&mbQ[bi][tyu]), pp);
        if (hasDn) mb_wait(s2u(&mbQ[bi][tyd]), pp);
        __syncwarp();
    };

    // P for plane in raw slot i1 (ring i0,i1,i2 = planes c-1,c,c+1) -> P slot qw.
    auto stepP = [&](int i0, int i1, int i2, int qw) {
        const int par = sCnt & 1;
        float2 zf = a2(a2(rF[i0], rF[i1]), rF[i2]);
        float2 zm = a2(a2(rM[i0], rM[i1]), rM[i2]);
        sA[par][ty][tx] = zf;
        sB[par][ty][tx] = zm;
        exchS(sCnt);
        float2 upF = sA[par][rup][tx], dnF = sA[par][rdn][tx];
        float2 upM = sB[par][rup][tx], dnM = sB[par][rdn][tx];
        float2 yf = a2(a2(upF, zf), dnF);
        float2 ym = a2(a2(upM, zm), dnM);
        float lF = __shfl_up_sync(FULL, yf.y, 1);
        float rG = __shfl_down_sync(FULL, yf.x, 1);
        float pF = yf.x + yf.y;
        float2 sF = make_float2(lF + pF, pF + rG);
        float lM = __shfl_up_sync(FULL, ym.y, 1);
        float rH = __shfl_down_sync(FULL, ym.x, 1);
        float pM = ym.x + ym.y;
        float2 sM = make_float2(lM + pM, pM + rH);
        float2 dF = f2ma(sF, NEGI, rF[i1]);
        float2 dM = f2ma(sM, NEGI, rM[i1]);
        pA[qw] = m2(dF, dM);
        pB[qw] = m2(dF, dF);
        pC[qw] = m2(dM, dM);
        sCnt++;
    };

    // box over P slots (i0,i1,i2) = P(j-1),P(j),P(j+1); score plane j.
    auto box2 = [&](int i0, int i1, int i2) {
        const int par = qCnt & 1;
        float2 zA = a2(a2(pA[i0], pA[i1]), pA[i2]);
        float2 zB = a2(a2(pB[i0], pB[i1]), pB[i2]);
        float2 zD = a2(a2(pC[i0], pC[i1]), pC[i2]);
        sQ0[par][ty][tx] = zA;
        sQ1[par][ty][tx] = zB;
        sQ2[par][ty][tx] = zD;
        exchQ(qCnt);
        float2 uA = sQ0[par][rup][tx], dA = sQ0[par][rdn][tx];
        float2 uB = sQ1[par][rup][tx], dB = sQ1[par][rdn][tx];
        float2 uD = sQ2[par][rup][tx], dD = sQ2[par][rdn][tx];
        uA = fixYup ? zA : uA;  dA = fixYdn ? zA : dA;
        uB = fixYup ? zB : uB;  dB = fixYdn ? zB : dB;
        uD = fixYup ? zD : uD;  dD = fixYdn ? zD : dD;
        float2 ybA = a2(a2(uA, zA), dA);
        float2 ybB = a2(a2(uB, zB), dB);
        float2 ybD = a2(a2(uD, zD), dD);
        float lA = __shfl_up_sync(FULL, ybA.y, 1);
        float rA = __shfl_down_sync(FULL, ybA.x, 1);
        float pA_ = ybA.x + ybA.y;
        float2 crA = make_float2((fixXlo ? ybA.x : lA) + pA_,
                                 pA_ + (fixXhi ? ybA.y : rA));
        float lB = __shfl_up_sync(FULL, ybB.y, 1);
        float rB = __shfl_down_sync(FULL, ybB.x, 1);
        float pB_ = ybB.x + ybB.y;
        float2 crB = make_float2((fixXlo ? ybB.x : lB) + pB_,
                                 pB_ + (fixXhi ? ybB.y : rB));
        float lD = __shfl_up_sync(FULL, ybD.y, 1);
        float rD = __shfl_down_sync(FULL, ybD.x, 1);
        float pD_ = ybD.x + ybD.y;
        float2 crD = make_float2((fixXlo ? ybD.x : lD) + pD_,
                                 pD_ + (fixXhi ? ybD.y : rD));
        float2 num = m2(crA, crA);
        float2 den = f2ma(crB, crD, EPS2);
        float2 zv  = make_float2(__fdividef(num.x, den.x),
                                 __fdividef(num.y, den.y));
        acc = f2ma(zv, mask, acc);
        qCnt++;
    };

    // ---- Prologue: raw slots end (0:Z0+1, 1:Z0+2, 2:Z0); P = P(Z0-1..Z0+1) ----
    if (Z0 == 0) {
        loadp(0, 2);
        loadp(1, 0);
        rF[1] = rF[2]; rM[1] = rM[2];
        stepP(1, 2, 0, 1);   // P(0): zsum = 2*r(0)+r(1), center r(0)
        pA[0] = pA[1]; pB[0] = pB[1]; pC[0] = pC[1];   // P(-1) := P(0)
        loadp(2, 1);
        stepP(2, 0, 1, 2);   // P(1)
    } else {
        loadp(Z0 - 2, 0);
        loadp(Z0 - 1, 1);
        loadp(Z0,     2);
        stepP(0, 1, 2, 0);   // P(Z0-1)
        loadp(Z0 + 1, 0);
        stepP(1, 2, 0, 1);   // P(Z0)
        loadp(Z0 + 2, 1);
        stepP(2, 0, 1, 2);   // P(Z0+1)
    }

    const int zlast = Z0 + ZC - 1;

    // ---- Main body. Entry: raw (s0,s1,s2) = planes (j+1, j+2, j), P = P(j-1..j+1).
    auto body = [&](int j, int s0, int s1, int s2) {
        loadp(j + 3, s2);        // overwrite oldest raw (plane j); clamped
        box2(s0, s1, s2);        // score plane j
        if (j < zlast) {
            if (j + 2 < NV) {
                stepP(s0, s1, s2, s0);   // P(j+2)
            } else {
                pA[s0] = pA[s2]; pB[s0] = pB[s2]; pC[s0] = pC[s2];  // replicate
            }
        }
    };

    for (int kb = 0; kb < ZC; kb += 3) {
        body(Z0 + kb,     0, 1, 2);
        body(Z0 + kb + 1, 1, 2, 0);
        body(Z0 + kb + 2, 2, 0, 1);
    }

    // ---- Reduction ----
    float t = acc.x + acc.y;
#pragma unroll
    for (int o = 16; o > 0; o >>= 1)
        t += __shfl_xor_sync(FULL, t, o);
    if (tx == 0) wsum[ty] = t;
    __syncthreads();
    if (tx == 0 && ty == 0) {
        float s = 0.0f;
#pragma unroll
        for (int i = 0; i < BYT; i++) s += wsum[i];
        atomicAdd(&out[b], s * (-1.0f / (float)NV3));
    }
}

extern "C" void kernel_launch(void* const* d_in, const int* in_sizes, int n_in,
                              void* d_out, int out_size) {
    const float* F = (const float*)d_in[0];
    const float* M = (const float*)d_in[1];
    float* out = (float*)d_out;

    const int B = (int)(in_sizes[0] / (long long)NV3);

    zero_out_kernel<<<1, 32>>>(out, out_size);

    dim3 block(32, BYT, 1);
    dim3 grid(NV / TOUTX, NV / TOUTY, B * ZCHUNKS);
    lcc_kernel<<<grid, block>>>(F, M, out);
}

// round 10
// speedup vs baseline: 1.3824x; 1.3824x over previous
#include <cuda_runtime.h>

// LCC over [B=2,1,192,192,192] fp32, fully fused z-sweep.
// Round-10: z-unroll-by-2. Each barrier phase processes TWO planes
// (double stepP / double box2): halves barriers per plane and gives each
// warp two independent dependency chains per phase. P ring = 4 slots,
// raw z-context as streaming sums {A,r3,r4,r5}. launch_bounds(256,2)
// (reg cap 128 -> no spills). Geometry identical to round-3 (32x8 thr,
// float2 lanes, COVY=16, TOUTY=12).

namespace {
constexpr int NV   = 192;
constexpr int NV2  = NV * NV;
constexpr long long NV3 = (long long)NV * NV2;
constexpr int BYT  = 8;
constexpr int RY   = 2;
constexpr int COVY = 16;
constexpr int TOUTX = 48;
constexpr int TOUTY = 12;
constexpr int ZCHUNKS = 8;
constexpr int ZC   = NV / ZCHUNKS;   // 24 planes -> 12 pairs (even)
constexpr float EPSV  = 1e-5f;
constexpr float INV27 = 1.0f / 27.0f;
constexpr unsigned FULL = 0xffffffffu;
}

__device__ __forceinline__ float2 a2(float2 a, float2 b) {
    float2 r;
    asm("{.reg .b64 ra,rb,rc;\n\t"
        "mov.b64 ra,{%2,%3};\n\t"
        "mov.b64 rb,{%4,%5};\n\t"
        "add.rn.f32x2 rc,ra,rb;\n\t"
        "mov.b64 {%0,%1},rc;}\n\t"
        : "=f"(r.x), "=f"(r.y)
        : "f"(a.x), "f"(a.y), "f"(b.x), "f"(b.y));
    return r;
}
__device__ __forceinline__ float2 m2(float2 a, float2 b) {
    float2 r;
    asm("{.reg .b64 ra,rb,rc;\n\t"
        "mov.b64 ra,{%2,%3};\n\t"
        "mov.b64 rb,{%4,%5};\n\t"
        "mul.rn.f32x2 rc,ra,rb;\n\t"
        "mov.b64 {%0,%1},rc;}\n\t"
        : "=f"(r.x), "=f"(r.y)
        : "f"(a.x), "f"(a.y), "f"(b.x), "f"(b.y));
    return r;
}
__device__ __forceinline__ float2 f2ma(float2 a, float2 b, float2 c) {
    float2 r;
    asm("{.reg .b64 ra,rb,rc,rd;\n\t"
        "mov.b64 ra,{%2,%3};\n\t"
        "mov.b64 rb,{%4,%5};\n\t"
        "mov.b64 rc,{%6,%7};\n\t"
        "fma.rn.f32x2 rd,ra,rb,rc;\n\t"
        "mov.b64 {%0,%1},rd;}\n\t"
        : "=f"(r.x), "=f"(r.y)
        : "f"(a.x), "f"(a.y), "f"(b.x), "f"(b.y), "f"(c.x), "f"(c.y));
    return r;
}

__global__ void zero_out_kernel(float* out, int n) {
    int i = blockIdx.x * blockDim.x + threadIdx.x;
    if (i < n) out[i] = 0.0f;
}

__global__ __launch_bounds__(256, 2)
void lcc_kernel(const float* __restrict__ gF,
                const float* __restrict__ gM,
                float* __restrict__ out)
{
    __shared__ float2 sA1[COVY][33], sA2[COVY][33];
    __shared__ float2 sB1[COVY][33], sB2[COVY][33];
    __shared__ float2 sQ1A[COVY][33], sQ1B[COVY][33], sQ1D[COVY][33];
    __shared__ float2 sQ2A[COVY][33], sQ2B[COVY][33], sQ2D[COVY][33];
    __shared__ float  wsum[BYT];

    const int tx  = threadIdx.x;
    const int ty  = threadIdx.y;
    const int yl0 = ty * RY;
    const int b   = blockIdx.z / ZCHUNKS;
    const int Z0  = (blockIdx.z % ZCHUNKS) * ZC;

    const int x_nom0 = (int)blockIdx.x * TOUTX - 2 + 2 * tx;   // even
    const int xbase  = min(max(x_nom0, 0), NV - 2);
    const bool fixlo  = (x_nom0 < 0);
    const bool fixhi  = (x_nom0 > NV - 2);
    const bool fixXlo = (x_nom0 == 0);
    const bool fixXhi = (x_nom0 + 1 == NV - 1);

    const int y_nom0 = (int)blockIdx.y * TOUTY - 2 + yl0;
    const bool fixYup = (y_nom0 == 0);
    const bool fixYdn = (y_nom0 + 1 == NV - 1);

    int yoff[RY];
#pragma unroll
    for (int i = 0; i < RY; i++)
        yoff[i] = min(max(y_nom0 + i, 0), NV - 1) * NV + xbase;

    const float* F = gF + (long long)b * NV3;
    const float* M = gM + (long long)b * NV3;

    // P ring: 4 z-slots (FM, FF, MM)
    float2 pA[4][RY], pB[4][RY], pC[4][RY];
    // raw streaming state: A=r(j+2)+r(j+3), r3=r(j+3), r4=r(j+4), r5=r(j+5)
    float2 aF[RY], f3[RY], f4[RY], f5[RY];
    float2 aM[RY], m3[RY], m4[RY], m5[RY];
    float2 acc = make_float2(0.f, 0.f);

    const float2 NEGI = make_float2(-INV27, -INV27);
    const float2 EPS2 = make_float2(EPSV, EPSV);

    const bool okl = (tx >= 1 && tx <= 24);
    float mrow[RY];
#pragma unroll
    for (int i = 0; i < RY; i++) {
        int yloc = yl0 + i;
        mrow[i] = (okl && yloc >= 2 && yloc < 2 + TOUTY) ? 1.0f : 0.0f;
    }

    const int rup = yl0 ? yl0 - 1 : 0;
    const int rdn = (yl0 + RY < COVY) ? yl0 + RY : COVY - 1;

    auto ldpair = [&](int z, float2 (&oF)[RY], float2 (&oM)[RY]) {
        z = min(max(z, 0), NV - 1);
        const float* fp = F + z * NV2;
        const float* mp = M + z * NV2;
#pragma unroll
        for (int i = 0; i < RY; i++) {
            float2 vF = __ldg(reinterpret_cast<const float2*>(fp + yoff[i]));
            float2 vM = __ldg(reinterpret_cast<const float2*>(mp + yoff[i]));
            oF[i].x = fixhi ? vF.y : vF.x;  oF[i].y = fixlo ? vF.x : vF.y;
            oM[i].x = fixhi ? vM.y : vM.x;  oM[i].y = fixlo ? vM.x : vM.y;
        }
    };

    // x-box shuffles + dF/dM + products for one plane. zf/zm are y-boxed sums;
    // centers cF/cM are the raw plane values.
    auto makeProducts = [&](float2 (&yf)[RY], float2 (&ym)[RY],
                            float2 (&cF)[RY], float2 (&cM)[RY], int s) {
#pragma unroll
        for (int i = 0; i < RY; i++) {
            float lF = __shfl_up_sync(FULL, yf[i].y, 1);
            float rG = __shfl_down_sync(FULL, yf[i].x, 1);
            float pF = yf[i].x + yf[i].y;
            float2 sF = make_float2(lF + pF, pF + rG);
            float lM = __shfl_up_sync(FULL, ym[i].y, 1);
            float rH = __shfl_down_sync(FULL, ym[i].x, 1);
            float pM = ym[i].x + ym[i].y;
            float2 sM = make_float2(lM + pM, pM + rH);
            float2 dF = f2ma(sF, NEGI, cF[i]);
            float2 dM = f2ma(sM, NEGI, cM[i]);
            pA[s][i] = m2(dF, dM);
            pB[s][i] = m2(dF, dF);
            pC[s][i] = m2(dM, dM);
        }
    };

    // Prologue single-plane stepP from explicit raw temps -> slot s.
    auto protoP = [&](float2 (&t0F)[RY], float2 (&t1F)[RY], float2 (&t2F)[RY],
                      float2 (&t0M)[RY], float2 (&t1M)[RY], float2 (&t2M)[RY],
                      int s) {
        float2 zf[RY], zm[RY];
#pragma unroll
        for (int i = 0; i < RY; i++) {
            zf[i] = a2(a2(t0F[i], t1F[i]), t2F[i]);
            zm[i] = a2(a2(t0M[i], t1M[i]), t2M[i]);
            sA1[yl0 + i][tx] = zf[i];
            sB1[yl0 + i][tx] = zm[i];
        }
        __syncthreads();
        float2 upF = sA1[rup][tx], dnF = sA1[rdn][tx];
        float2 upM = sB1[rup][tx], dnM = sB1[rdn][tx];
        float2 yf[RY], ym[RY];
        yf[0] = a2(a2(upF, zf[0]), zf[1]);  yf[1] = a2(a2(zf[0], zf[1]), dnF);
        ym[0] = a2(a2(upM, zm[0]), zm[1]);  ym[1] = a2(a2(zm[0], zm[1]), dnM);
        makeProducts(yf, ym, t1F, t1M, s);
        __syncthreads();   // allow sA1/sB1 reuse
    };

    // Score one plane from its P z-sums (regs) + smem neighbor exchange.
    auto scorePlane = [&](float2 (&zA)[RY], float2 (&zB)[RY], float2 (&zD)[RY],
                          float2 (*qA)[33], float2 (*qB)[33], float2 (*qD)[33]) {
        float2 uA = qA[rup][tx], dA = qA[rdn][tx];
        float2 uB = qB[rup][tx], dB = qB[rdn][tx];
        float2 uD = qD[rup][tx], dD = qD[rdn][tx];
        uA = fixYup ? zA[0] : uA;  dA = fixYdn ? zA[1] : dA;
        uB = fixYup ? zB[0] : uB;  dB = fixYdn ? zB[1] : dB;
        uD = fixYup ? zD[0] : uD;  dD = fixYdn ? zD[1] : dD;
        float2 ybA[RY], ybB[RY], ybD[RY];
        ybA[0] = a2(a2(uA, zA[0]), zA[1]);  ybA[1] = a2(a2(zA[0], zA[1]), dA);
        ybB[0] = a2(a2(uB, zB[0]), zB[1]);  ybB[1] = a2(a2(zB[0], zB[1]), dB);
        ybD[0] = a2(a2(uD, zD[0]), zD[1]);  ybD[1] = a2(a2(zD[0], zD[1]), dD);
#pragma unroll
        for (int i = 0; i < RY; i++) {
            float lA = __shfl_up_sync(FULL, ybA[i].y, 1);
            float rA = __shfl_down_sync(FULL, ybA[i].x, 1);
            float pA_ = ybA[i].x + ybA[i].y;
            float2 crA = make_float2((fixXlo ? ybA[i].x : lA) + pA_,
                                     pA_ + (fixXhi ? ybA[i].y : rA));
            float lB = __shfl_up_sync(FULL, ybB[i].y, 1);
            float rB = __shfl_down_sync(FULL, ybB[i].x, 1);
            float pB_ = ybB[i].x + ybB[i].y;
            float2 crB = make_float2((fixXlo ? ybB[i].x : lB) + pB_,
                                     pB_ + (fixXhi ? ybB[i].y : rB));
            float lD = __shfl_up_sync(FULL, ybD[i].y, 1);
            float rD = __shfl_down_sync(FULL, ybD[i].x, 1);
            float pD_ = ybD[i].x + ybD[i].y;
            float2 crD = make_float2((fixXlo ? ybD[i].x : lD) + pD_,
                                     pD_ + (fixXhi ? ybD[i].y : rD));
            float2 num = m2(crA, crA);
            float2 den = f2ma(crB, crD, EPS2);
            float2 zv  = make_float2(__fdividef(num.x, den.x),
                                     __fdividef(num.y, den.y));
            acc = f2ma(zv, make_float2(mrow[i], mrow[i]), acc);
        }
    };

    // ---- Prologue: P(Z0-1..Z0+2) -> slots 0..3; prime raw streaming ----
    {
        float2 t0F[RY], t1F[RY], t2F[RY], t0M[RY], t1M[RY], t2M[RY];
        ldpair(Z0 - 2, t0F, t0M);
        ldpair(Z0 - 1, t1F, t1M);
        ldpair(Z0,     t2F, t2M);
        protoP(t0F, t1F, t2F, t0M, t1M, t2M, 0);   // P(Z0-1)
#pragma unroll
        for (int i = 0; i < RY; i++) { t0F[i] = t1F[i]; t1F[i] = t2F[i];
                                       t0M[i] = t1M[i]; t1M[i] = t2M[i]; }
        ldpair(Z0 + 1, t2F, t2M);
        protoP(t0F, t1F, t2F, t0M, t1M, t2M, 1);   // P(Z0)
#pragma unroll
        for (int i = 0; i < RY; i++) { t0F[i] = t1F[i]; t1F[i] = t2F[i];
                                       t0M[i] = t1M[i]; t1M[i] = t2M[i]; }
        ldpair(Z0 + 2, t2F, t2M);
        protoP(t0F, t1F, t2F, t0M, t1M, t2M, 2);   // P(Z0+1)
#pragma unroll
        for (int i = 0; i < RY; i++) { t0F[i] = t1F[i]; t1F[i] = t2F[i];
                                       t0M[i] = t1M[i]; t1M[i] = t2M[i]; }
        ldpair(Z0 + 3, t2F, t2M);
        protoP(t0F, t1F, t2F, t0M, t1M, t2M, 3);   // P(Z0+2)
        if (Z0 == 0) {
#pragma unroll
            for (int i = 0; i < RY; i++) {   // P(-1) := P(0)
                pA[0][i] = pA[1][i]; pB[0][i] = pB[1][i]; pC[0][i] = pC[1][i];
            }
        }
        // prime streaming: t1 = r(Z0+2), t2 = r(Z0+3)
#pragma unroll
        for (int i = 0; i < RY; i++) {
            aF[i] = a2(t1F[i], t2F[i]);  f3[i] = t2F[i];
            aM[i] = a2(t1M[i], t2M[i]);  m3[i] = t2M[i];
        }
        ldpair(Z0 + 4, f4, m4);
        ldpair(Z0 + 5, f5, m5);
    }

    // ---- Main loop: process pairs (j, j+1). Slots at entry:
    // s0=P(j-1), s1=P(j), s2=P(j+1), s3=P(j+2). ----
    auto pairBody = [&](int j, int s0, int s1, int s2, int s3) {
        if (j + 2 >= NV) {           // replicate: P(NV) := P(NV-1)
#pragma unroll
            for (int i = 0; i < RY; i++) {
                pA[s3][i] = pA[s2][i]; pB[s3][i] = pB[s2][i]; pC[s3][i] = pC[s2][i];
            }
        }
        // ===== PHASE B: score planes j and j+1 (one barrier) =====
        float2 z1A[RY], z1B[RY], z1D[RY], z2A[RY], z2B[RY], z2D[RY];
#pragma unroll
        for (int i = 0; i < RY; i++) {
            z1A[i] = a2(a2(pA[s0][i], pA[s1][i]), pA[s2][i]);
            z1B[i] = a2(a2(pB[s0][i], pB[s1][i]), pB[s2][i]);
            z1D[i] = a2(a2(pC[s0][i], pC[s1][i]), pC[s2][i]);
            z2A[i] = a2(a2(pA[s1][i], pA[s2][i]), pA[s3][i]);
            z2B[i] = a2(a2(pB[s1][i], pB[s2][i]), pB[s3][i]);
            z2D[i] = a2(a2(pC[s1][i], pC[s2][i]), pC[s3][i]);
            sQ1A[yl0 + i][tx] = z1A[i];
            sQ1B[yl0 + i][tx] = z1B[i];
            sQ1D[yl0 + i][tx] = z1D[i];
            sQ2A[yl0 + i][tx] = z2A[i];
            sQ2B[yl0 + i][tx] = z2B[i];
            sQ2D[yl0 + i][tx] = z2D[i];
        }
        __syncthreads();
        scorePlane(z1A, z1B, z1D, sQ1A, sQ1B, sQ1D);
        scorePlane(z2A, z2B, z2D, sQ2A, sQ2B, sQ2D);

        // ===== PHASE A: produce P(j+3)->s0, P(j+4)->s1 (one barrier) =====
        if (j + 2 < Z0 + ZC) {
            float2 zf1[RY], zf2[RY], zm1[RY], zm2[RY];
#pragma unroll
            for (int i = 0; i < RY; i++) {
                zf1[i] = a2(aF[i], f4[i]);                 // zsum(j+3)
                zf2[i] = a2(a2(f3[i], f4[i]), f5[i]);      // zsum(j+4)
                zm1[i] = a2(aM[i], m4[i]);
                zm2[i] = a2(a2(m3[i], m4[i]), m5[i]);
                sA1[yl0 + i][tx] = zf1[i];
                sA2[yl0 + i][tx] = zf2[i];
                sB1[yl0 + i][tx] = zm1[i];
                sB2[yl0 + i][tx] = zm2[i];
            }
            __syncthreads();
            {   // plane j+3 (center f3) -> slot s0
                float2 upF = sA1[rup][tx], dnF = sA1[rdn][tx];
                float2 upM = sB1[rup][tx], dnM = sB1[rdn][tx];
                float2 yf[RY], ym[RY];
                yf[0] = a2(a2(upF, zf1[0]), zf1[1]);  yf[1] = a2(a2(zf1[0], zf1[1]), dnF);
                ym[0] = a2(a2(upM, zm1[0]), zm1[1]);  ym[1] = a2(a2(zm1[0], zm1[1]), dnM);
                makeProducts(yf, ym, f3, m3, s0);
            }
            {   // plane j+4 (center f4) -> slot s1
                float2 upF = sA2[rup][tx], dnF = sA2[rdn][tx];
                float2 upM = sB2[rup][tx], dnM = sB2[rdn][tx];
                float2 yf[RY], ym[RY];
                yf[0] = a2(a2(upF, zf2[0]), zf2[1]);  yf[1] = a2(a2(zf2[0], zf2[1]), dnF);
                ym[0] = a2(a2(upM, zm2[0]), zm2[1]);  ym[1] = a2(a2(zm2[0], zm2[1]), dnM);
                makeProducts(yf, ym, f4, m4, s1);
            }
            // streaming update + prefetch next two planes
#pragma unroll
            for (int i = 0; i < RY; i++) {
                aF[i] = a2(f4[i], f5[i]);  f3[i] = f5[i];
                aM[i] = a2(m4[i], m5[i]);  m3[i] = m5[i];
            }
            ldpair(j + 6, f4, m4);
            ldpair(j + 7, f5, m5);
        }
    };

    for (int pp = 0; pp < ZC / 2; pp += 2) {
        pairBody(Z0 + 2 * pp,     0, 1, 2, 3);
        pairBody(Z0 + 2 * pp + 2, 2, 3, 0, 1);
    }

    // ---- Reduction ----
    float t = acc.x + acc.y;
#pragma unroll
    for (int o = 16; o > 0; o >>= 1)
        t += __shfl_xor_sync(FULL, t, o);
    if (tx == 0) wsum[ty] = t;
    __syncthreads();
    if (tx == 0 && ty == 0) {
        float s = 0.0f;
#pragma unroll
        for (int i = 0; i < BYT; i++) s += wsum[i];
        atomicAdd(&out[b], s * (-1.0f / (float)NV3));
    }
}

extern "C" void kernel_launch(void* const* d_in, const int* in_sizes, int n_in,
                              void* d_out, int out_size) {
    const float* F = (const float*)d_in[0];
    const float* M = (const float*)d_in[1];
    float* out = (float*)d_out;

    const int B = (int)(in_sizes[0] / (long long)NV3);

    zero_out_kernel<<<1, 32>>>(out, out_size);

    dim3 block(32, BYT, 1);
    dim3 grid(NV / TOUTX, NV / TOUTY, B * ZCHUNKS);
    lcc_kernel<<<grid, block>>>(F, M, out);
}

// round 11
// speedup vs baseline: 1.8356x; 1.3278x over previous
#include <cuda_runtime.h>

// LCC over [B=2,1,192,192,192] fp32, fully fused z-sweep.
// Round-11: round-3 kernel (best: 94.7us) with 192-thread CTAs (32x6,
// COVY=12, TOUTY=8). Per-thread code identical (natural ~80 regs), but
// 192thr x 80regs x 4 CTAs = 61440 < 64K -> 4 independent barrier groups
// per SM (the round-2 regime that measured 75.6% issue).

namespace {
constexpr int NV   = 192;
constexpr int NV2  = NV * NV;
constexpr long long NV3 = (long long)NV * NV2;
constexpr int BYT  = 6;
constexpr int RY   = 2;
constexpr int COVY = BYT * RY;      // 12 covered rows
constexpr int TOUTX = 48;           // outputs/block in x (lanes cover 64)
constexpr int TOUTY = COVY - 4;     // 8
constexpr int ZCHUNKS = 8;
constexpr int ZC   = NV / ZCHUNKS;  // 24 (divisible by 3)
constexpr float EPSV  = 1e-5f;
constexpr float INV27 = 1.0f / 27.0f;
constexpr unsigned FULL = 0xffffffffu;
}

__device__ __forceinline__ float2 a2(float2 a, float2 b) {
    float2 r;
    asm("{.reg .b64 ra,rb,rc;\n\t"
        "mov.b64 ra,{%2,%3};\n\t"
        "mov.b64 rb,{%4,%5};\n\t"
        "add.rn.f32x2 rc,ra,rb;\n\t"
        "mov.b64 {%0,%1},rc;}\n\t"
        : "=f"(r.x), "=f"(r.y)
        : "f"(a.x), "f"(a.y), "f"(b.x), "f"(b.y));
    return r;
}
__device__ __forceinline__ float2 m2(float2 a, float2 b) {
    float2 r;
    asm("{.reg .b64 ra,rb,rc;\n\t"
        "mov.b64 ra,{%2,%3};\n\t"
        "mov.b64 rb,{%4,%5};\n\t"
        "mul.rn.f32x2 rc,ra,rb;\n\t"
        "mov.b64 {%0,%1},rc;}\n\t"
        : "=f"(r.x), "=f"(r.y)
        : "f"(a.x), "f"(a.y), "f"(b.x), "f"(b.y));
    return r;
}
__device__ __forceinline__ float2 f2ma(float2 a, float2 b, float2 c) {
    float2 r;
    asm("{.reg .b64 ra,rb,rc,rd;\n\t"
        "mov.b64 ra,{%2,%3};\n\t"
        "mov.b64 rb,{%4,%5};\n\t"
        "mov.b64 rc,{%6,%7};\n\t"
        "fma.rn.f32x2 rd,ra,rb,rc;\n\t"
        "mov.b64 {%0,%1},rd;}\n\t"
        : "=f"(r.x), "=f"(r.y)
        : "f"(a.x), "f"(a.y), "f"(b.x), "f"(b.y), "f"(c.x), "f"(c.y));
    return r;
}

__global__ void zero_out_kernel(float* out, int n) {
    int i = blockIdx.x * blockDim.x + threadIdx.x;
    if (i < n) out[i] = 0.0f;
}

__global__ __launch_bounds__(32 * BYT, 4)
void lcc_kernel(const float* __restrict__ gF,
                const float* __restrict__ gM,
                float* __restrict__ out)
{
    __shared__ float2 sA [COVY][33];
    __shared__ float2 sB [COVY][33];
    __shared__ float2 sQ0[COVY][33];
    __shared__ float2 sQ1[COVY][33];
    __shared__ float2 sQ2[COVY][33];
    __shared__ float  wsum[BYT];

    const int tx  = threadIdx.x;
    const int ty  = threadIdx.y;
    const int yl0 = ty * RY;
    const int b   = blockIdx.z / ZCHUNKS;
    const int Z0  = (blockIdx.z % ZCHUNKS) * ZC;

    const int x_nom0 = (int)blockIdx.x * TOUTX - 2 + 2 * tx;   // even
    const int xbase  = min(max(x_nom0, 0), NV - 2);
    const bool fixlo  = (x_nom0 < 0);
    const bool fixhi  = (x_nom0 > NV - 2);
    const bool fixXlo = (x_nom0 == 0);
    const bool fixXhi = (x_nom0 + 1 == NV - 1);

    const int y_nom0 = (int)blockIdx.y * TOUTY - 2 + yl0;
    const bool fixYup = (y_nom0 == 0);
    const bool fixYdn = (y_nom0 + 1 == NV - 1);

    int yoff[RY];
#pragma unroll
    for (int i = 0; i < RY; i++)
        yoff[i] = min(max(y_nom0 + i, 0), NV - 1) * NV + xbase;

    const float* F = gF + (long long)b * NV3;
    const float* M = gM + (long long)b * NV3;

    float2 rF[3][RY], rM[3][RY];               // raw plane ring
    float2 pA[3][RY], pB[3][RY], pC[3][RY];    // P plane ring (FM, FF, MM)
    float2 acc = make_float2(0.f, 0.f);

    const float2 NEGI = make_float2(-INV27, -INV27);
    const float2 EPS2 = make_float2(EPSV, EPSV);

    const bool okl = (tx >= 1 && tx <= 24);
    float mrow[RY];
#pragma unroll
    for (int i = 0; i < RY; i++) {
        int yloc = yl0 + i;
        mrow[i] = (okl && yloc >= 2 && yloc < 2 + TOUTY) ? 1.0f : 0.0f;
    }

    auto loadp = [&](int z, float2 (&oF)[RY], float2 (&oM)[RY]) {
        z = min(max(z, 0), NV - 1);
        const float* fp = F + z * NV2;
        const float* mp = M + z * NV2;
#pragma unroll
        for (int i = 0; i < RY; i++) {
            float2 vF = __ldg(reinterpret_cast<const float2*>(fp + yoff[i]));
            float2 vM = __ldg(reinterpret_cast<const float2*>(mp + yoff[i]));
            oF[i].x = fixhi ? vF.y : vF.x;  oF[i].y = fixlo ? vF.x : vF.y;
            oM[i].x = fixhi ? vM.y : vM.x;  oM[i].y = fixlo ? vM.x : vM.y;
        }
    };

    const int rup = yl0 ? yl0 - 1 : 0;
    const int rdn = (yl0 + RY < COVY) ? yl0 + RY : COVY - 1;

    // P for the plane in raw slot i1 (i0,i1,i2 = planes c-1,c,c+1) -> slot qw.
    auto stepP = [&](int i0, int i1, int i2, int qw) {
        float2 zf[RY], zm[RY];
#pragma unroll
        for (int i = 0; i < RY; i++) {
            zf[i] = a2(a2(rF[i0][i], rF[i1][i]), rF[i2][i]);
            zm[i] = a2(a2(rM[i0][i], rM[i1][i]), rM[i2][i]);
            sA[yl0 + i][tx] = zf[i];
            sB[yl0 + i][tx] = zm[i];
        }
        __syncthreads();
        float2 upF = sA[rup][tx], dnF = sA[rdn][tx];
        float2 upM = sB[rup][tx], dnM = sB[rdn][tx];
        float2 yf[RY], ym[RY];
        yf[0] = a2(a2(upF, zf[0]), zf[1]);  yf[1] = a2(a2(zf[0], zf[1]), dnF);
        ym[0] = a2(a2(upM, zm[0]), zm[1]);  ym[1] = a2(a2(zm[0], zm[1]), dnM);
        __syncthreads();  // guards sA/sB reuse next call
#pragma unroll
        for (int i = 0; i < RY; i++) {
            float lF = __shfl_up_sync(FULL, yf[i].y, 1);
            float rG = __shfl_down_sync(FULL, yf[i].x, 1);
            float pF = yf[i].x + yf[i].y;
            float2 sF = make_float2(lF + pF, pF + rG);
            float lM = __shfl_up_sync(FULL, ym[i].y, 1);
            float rH = __shfl_down_sync(FULL, ym[i].x, 1);
            float pM = ym[i].x + ym[i].y;
            float2 sM = make_float2(lM + pM, pM + rH);
            float2 dF = f2ma(sF, NEGI, rF[i1][i]);
            float2 dM = f2ma(sM, NEGI, rM[i1][i]);
            pA[qw][i] = m2(dF, dM);
            pB[qw][i] = m2(dF, dF);
            pC[qw][i] = m2(dM, dM);
        }
    };

    // second box over P slots (i0,i1,i2) = P(j-1),P(j),P(j+1); score plane j.
    auto box2 = [&](int i0, int i1, int i2) {
        float2 zA[RY], zB[RY], zD[RY];
#pragma unroll
        for (int i = 0; i < RY; i++) {
            zA[i] = a2(a2(pA[i0][i], pA[i1][i]), pA[i2][i]);
            zB[i] = a2(a2(pB[i0][i], pB[i1][i]), pB[i2][i]);
            zD[i] = a2(a2(pC[i0][i], pC[i1][i]), pC[i2][i]);
            sQ0[yl0 + i][tx] = zA[i];
            sQ1[yl0 + i][tx] = zB[i];
            sQ2[yl0 + i][tx] = zD[i];
        }
        __syncthreads();
        float2 uA = sQ0[rup][tx], dA = sQ0[rdn][tx];
        float2 uB = sQ1[rup][tx], dB = sQ1[rdn][tx];
        float2 uD = sQ2[rup][tx], dD = sQ2[rdn][tx];
        __syncthreads();  // guards sQ reuse next call
        uA = fixYup ? zA[0] : uA;  dA = fixYdn ? zA[1] : dA;
        uB = fixYup ? zB[0] : uB;  dB = fixYdn ? zB[1] : dB;
        uD = fixYup ? zD[0] : uD;  dD = fixYdn ? zD[1] : dD;
        float2 ybA[RY], ybB[RY], ybD[RY];
        ybA[0] = a2(a2(uA, zA[0]), zA[1]);  ybA[1] = a2(a2(zA[0], zA[1]), dA);
        ybB[0] = a2(a2(uB, zB[0]), zB[1]);  ybB[1] = a2(a2(zB[0], zB[1]), dB);
        ybD[0] = a2(a2(uD, zD[0]), zD[1]);  ybD[1] = a2(a2(zD[0], zD[1]), dD);
#pragma unroll
        for (int i = 0; i < RY; i++) {
            float lA = __shfl_up_sync(FULL, ybA[i].y, 1);
            float rA = __shfl_down_sync(FULL, ybA[i].x, 1);
            float pA_ = ybA[i].x + ybA[i].y;
            float2 crA = make_float2((fixXlo ? ybA[i].x : lA) + pA_,
                                     pA_ + (fixXhi ? ybA[i].y : rA));
            float lB = __shfl_up_sync(FULL, ybB[i].y, 1);
            float rB = __shfl_down_sync(FULL, ybB[i].x, 1);
            float pB_ = ybB[i].x + ybB[i].y;
            float2 crB = make_float2((fixXlo ? ybB[i].x : lB) + pB_,
                                     pB_ + (fixXhi ? ybB[i].y : rB));
            float lD = __shfl_up_sync(FULL, ybD[i].y, 1);
            float rD = __shfl_down_sync(FULL, ybD[i].x, 1);
            float pD_ = ybD[i].x + ybD[i].y;
            float2 crD = make_float2((fixXlo ? ybD[i].x : lD) + pD_,
                                     pD_ + (fixXhi ? ybD[i].y : rD));
            float2 num = m2(crA, crA);
            float2 den = f2ma(crB, crD, EPS2);
            float2 zv  = make_float2(__fdividef(num.x, den.x),
                                     __fdividef(num.y, den.y));
            acc = f2ma(zv, make_float2(mrow[i], mrow[i]), acc);
        }
    };

    // ---- Prologue: raw slots end (0:Z0+1, 1:Z0+2, 2:Z0); P = P(Z0-1..Z0+1) ----
    if (Z0 == 0) {
        loadp(0, rF[2], rM[2]);
        loadp(1, rF[0], rM[0]);
#pragma unroll
        for (int i = 0; i < RY; i++) { rF[1][i] = rF[2][i]; rM[1][i] = rM[2][i]; }
        stepP(1, 2, 0, 1);   // P(0); zsum = 2*r(0)+r(1)
#pragma unroll
        for (int i = 0; i < RY; i++) {   // P(-1) := P(0)
            pA[0][i] = pA[1][i]; pB[0][i] = pB[1][i]; pC[0][i] = pC[1][i];
        }
        loadp(2, rF[1], rM[1]);
        stepP(2, 0, 1, 2);   // P(1)
    } else {
        loadp(Z0 - 2, rF[0], rM[0]);
        loadp(Z0 - 1, rF[1], rM[1]);
        loadp(Z0,     rF[2], rM[2]);
        stepP(0, 1, 2, 0);   // P(Z0-1)
        loadp(Z0 + 1, rF[0], rM[0]);
        stepP(1, 2, 0, 1);   // P(Z0)
        loadp(Z0 + 2, rF[1], rM[1]);
        stepP(2, 0, 1, 2);   // P(Z0+1)
    }

    const int zlast = Z0 + ZC - 1;

    // ---- Main body. Entry: raw (s0,s1,s2) = planes (j+1, j+2, j), P = P(j-1..j+1).
    auto body = [&](int j, int s0, int s1, int s2) {
        loadp(j + 3, rF[s2], rM[s2]);   // overwrite oldest raw (plane j); clamped
        box2(s0, s1, s2);               // score plane j
        if (j < zlast) {
            if (j + 2 < NV) {
                stepP(s0, s1, s2, s0);  // P(j+2)
            } else {
#pragma unroll
                for (int i = 0; i < RY; i++) {  // P(j+2) := P(NV-1)
                    pA[s0][i] = pA[s2][i];
                    pB[s0][i] = pB[s2][i];
                    pC[s0][i] = pC[s2][i];
                }
            }
        }
    };

    for (int kb = 0; kb < ZC; kb += 3) {
        body(Z0 + kb,     0, 1, 2);
        body(Z0 + kb + 1, 1, 2, 0);
        body(Z0 + kb + 2, 2, 0, 1);
    }

    // ---- Reduction ----
    float t = acc.x + acc.y;
#pragma unroll
    for (int o = 16; o > 0; o >>= 1)
        t += __shfl_xor_sync(FULL, t, o);
    if (tx == 0) wsum[ty] = t;
    __syncthreads();
    if (tx == 0 && ty == 0) {
        float s = 0.0f;
#pragma unroll
        for (int i = 0; i < BYT; i++) s += wsum[i];
        atomicAdd(&out[b], s * (-1.0f / (float)NV3));
    }
}

extern "C" void kernel_launch(void* const* d_in, const int* in_sizes, int n_in,
                              void* d_out, int out_size) {
    const float* F = (const float*)d_in[0];
    const float* M = (const float*)d_in[1];
    float* out = (float*)d_out;

    const int B = (int)(in_sizes[0] / (long long)NV3);

    zero_out_kernel<<<1, 32>>>(out, out_size);

    dim3 block(32, BYT, 1);
    dim3 grid(NV / TOUTX, NV / TOUTY, B * ZCHUNKS);
    lcc_kernel<<<grid, block>>>(F, M, out);
}